// round 3
// baseline (speedup 1.0000x reference)
#include <cuda_runtime.h>

// Problem constants
#define GDIM   64
#define SPAT   (GDIM*GDIM*GDIM)      // 262144 voxels per batch
#define BATCH  2
#define NTOT   (BATCH*SPAT)          // 524288 total voxels
#define NCH    16
#define HID    128
#define NGROWN 12

// Scratch (static __device__ — no runtime allocation allowed).
// IMPORTANT: these symbols are referenced ONLY from device code. Passing them
// as kernel arguments from the host passes the host shadow address, which on
// GB300 (ATS) is silently dereferenceable and reads zeros.
__device__ float g_bufA[128u * (unsigned)NTOT];  // perc (64 rows) then h2 (128 rows)
__device__ float g_bufB[128u * (unsigned)NTOT];  // h1
__device__ float g_wT1[64 * 128];    // w1 transposed: [k][o]
__device__ float g_wT2[128 * 128];   // w2 transposed: [k][o]

// ---------------------------------------------------------------------------
// Weight transpose: w[o][k] -> wT[k][o]
// ---------------------------------------------------------------------------
__global__ void k_transpose(const float* __restrict__ w1,
                            const float* __restrict__ w2) {
    int tid = blockIdx.x * blockDim.x + threadIdx.x;
    int stride = gridDim.x * blockDim.x;
    for (int i = tid; i < 64 * 128; i += stride) {
        int o = i & 127, k = i >> 7;
        g_wT1[k * 128 + o] = w1[o * 64 + k];
    }
    for (int i = tid; i < 128 * 128; i += stride) {
        int o = i & 127, k = i >> 7;
        g_wT2[k * 128 + o] = w2[o * 128 + k];
    }
}

// ---------------------------------------------------------------------------
// Perceive: depthwise [identity, sobel_x, sobel_y, sobel_z], edge-clamped.
// Block = 8x8x8 voxels, shared halo tile 10x10x10, one channel at a time.
// Writes channel-major perc[ch][v] into g_bufA (coalesced).
// ---------------------------------------------------------------------------
__global__ void k_perceive(const float* __restrict__ state) {
    __shared__ float t[10][10][10];
    const int lx = threadIdx.x, ly = threadIdx.y, lz = threadIdx.z;
    const int tid = (lz * 8 + ly) * 8 + lx;
    const int x0 = blockIdx.x * 8;
    const int y0 = blockIdx.y * 8;
    const int b  = blockIdx.z >> 3;
    const int z0 = (blockIdx.z & 7) * 8;
    const int gx = x0 + lx, gy = y0 + ly, gz = z0 + lz;
    const int sidx = (gz << 12) + (gy << 6) + gx;
    const int v = b * SPAT + sidx;
    const float s3[3] = {1.f, 2.f, 1.f};

    for (int c = 0; c < NCH; ++c) {
        const float* sc = state + (size_t)(b * NCH + c) * SPAT;
        for (int i = tid; i < 1000; i += 512) {
            int iz = i / 100;
            int iy = (i / 10) % 10;
            int ix = i % 10;
            int cz = min(max(z0 + iz - 1, 0), GDIM - 1);
            int cy = min(max(y0 + iy - 1, 0), GDIM - 1);
            int cx = min(max(x0 + ix - 1, 0), GDIM - 1);
            t[iz][iy][ix] = sc[(cz << 12) + (cy << 6) + cx];
        }
        __syncthreads();

        float ident = t[lz + 1][ly + 1][lx + 1];
        float sx = 0.f, sy = 0.f, sz = 0.f;
#pragma unroll
        for (int a = 0; a < 3; ++a) {
#pragma unroll
            for (int bb = 0; bb < 3; ++bb) {
                float r0 = t[lz + a][ly + bb][lx + 0];
                float r1 = t[lz + a][ly + bb][lx + 1];
                float r2 = t[lz + a][ly + bb][lx + 2];
                float sum = r0 + 2.f * r1 + r2;
                sx += (s3[a] * s3[bb]) * (r2 - r0);
                sy += (s3[a] * (float)(bb - 1)) * sum;
                sz += ((float)(a - 1) * s3[bb]) * sum;
            }
        }
        sx *= (1.f / 16.f); sy *= (1.f / 16.f); sz *= (1.f / 16.f);

        g_bufA[(0 * NCH + c) * NTOT + v] = ident;
        g_bufA[(1 * NCH + c) * NTOT + v] = sx;
        g_bufA[(2 * NCH + c) * NTOT + v] = sy;
        g_bufA[(3 * NCH + c) * NTOT + v] = sz;
        __syncthreads();
    }
}

// ---------------------------------------------------------------------------
// Pointwise GEMM + bias + ReLU. Buffers selected by template K inside device
// code (never passed from host).
//   K=64 : A = g_bufA (perc),  Bt = g_wT1, C = g_bufB (h1)
//   K=128: A = g_bufB (h1),    Bt = g_wT2, C = g_bufA (h2)
// Block tile: 64 voxels x 128 outputs; 256 threads; 4v x 8o register tile.
// ---------------------------------------------------------------------------
template <int K>
__global__ void __launch_bounds__(256) k_gemm(const float* __restrict__ bias) {
    const float* A  = (K == 64) ? g_bufA : g_bufB;
    const float* Bt = (K == 64) ? g_wT1  : g_wT2;
    float*       C  = (K == 64) ? g_bufB : g_bufA;

    __shared__ float sA[16][64];
    __shared__ float sB[16][128];

    const int tid = threadIdx.x;
    const int tx = tid & 15;    // voxel group  -> v0 = tx*4
    const int ty = tid >> 4;    // output group -> o0 = ty*8
    const int vbase = blockIdx.x * 64;

    const int la_r = tid >> 4;          // 0..15
    const int la_c = (tid & 15) * 4;    // 0..60
    const int lb_r = tid >> 5;          // 0..7
    const int lb_c = (tid & 31) * 4;    // 0..124

    float acc[8][4];
#pragma unroll
    for (int oo = 0; oo < 8; ++oo)
#pragma unroll
        for (int vv = 0; vv < 4; ++vv) acc[oo][vv] = 0.f;

    for (int k0 = 0; k0 < K; k0 += 16) {
        *(float4*)&sA[la_r][la_c] =
            *(const float4*)&A[(k0 + la_r) * NTOT + vbase + la_c];
        *(float4*)&sB[lb_r][lb_c] =
            *(const float4*)&Bt[(k0 + lb_r) * 128 + lb_c];
        *(float4*)&sB[lb_r + 8][lb_c] =
            *(const float4*)&Bt[(k0 + lb_r + 8) * 128 + lb_c];
        __syncthreads();

#pragma unroll
        for (int kk = 0; kk < 16; ++kk) {
            float4 a4 = *(const float4*)&sA[kk][tx * 4];
            float4 b0 = *(const float4*)&sB[kk][ty * 8];
            float4 b1 = *(const float4*)&sB[kk][ty * 8 + 4];
            float av[4] = {a4.x, a4.y, a4.z, a4.w};
            float bv[8] = {b0.x, b0.y, b0.z, b0.w, b1.x, b1.y, b1.z, b1.w};
#pragma unroll
            for (int oo = 0; oo < 8; ++oo)
#pragma unroll
                for (int vv = 0; vv < 4; ++vv)
                    acc[oo][vv] += bv[oo] * av[vv];
        }
        __syncthreads();
    }

#pragma unroll
    for (int oo = 0; oo < 8; ++oo) {
        int o = ty * 8 + oo;
        float bval = bias[o];
        float4 r;
        r.x = fmaxf(acc[oo][0] + bval, 0.f);
        r.y = fmaxf(acc[oo][1] + bval, 0.f);
        r.z = fmaxf(acc[oo][2] + bval, 0.f);
        r.w = fmaxf(acc[oo][3] + bval, 0.f);
        *(float4*)&C[o * NTOT + vbase + tx * 4] = r;
    }
}

// ---------------------------------------------------------------------------
// Final: GEMM3 (128 -> 12) + NCA update epilogue. h2 read from g_bufA
// directly (device symbol).
// ---------------------------------------------------------------------------
__global__ void __launch_bounds__(256) k_final(const float* __restrict__ w3,
                                               const float* __restrict__ b3,
                                               const float* __restrict__ state,
                                               float* __restrict__ out) {
    __shared__ float sW[128 * 12];   // sW[k][j] = w3[j][k]
    const int tid = threadIdx.x;
    for (int i = tid; i < 128 * 12; i += 256) {
        int k = i / 12;
        int j = i - k * 12;
        sW[k * 12 + j] = w3[j * 128 + k];
    }
    __syncthreads();

    const int v = blockIdx.x * 256 + tid;

    float acc[12];
#pragma unroll
    for (int j = 0; j < 12; ++j) acc[j] = 0.f;

#pragma unroll 4
    for (int k = 0; k < 128; ++k) {
        float x = g_bufA[k * NTOT + v];
        const float4* wr = (const float4*)&sW[k * 12];
        float4 w0 = wr[0], w1v = wr[1], w2v = wr[2];
        acc[0] += x * w0.x;  acc[1] += x * w0.y;
        acc[2] += x * w0.z;  acc[3] += x * w0.w;
        acc[4] += x * w1v.x; acc[5] += x * w1v.y;
        acc[6] += x * w1v.z; acc[7] += x * w1v.w;
        acc[8] += x * w2v.x; acc[9] += x * w2v.y;
        acc[10] += x * w2v.z; acc[11] += x * w2v.w;
    }

    const int b = v >> 18;            // SPAT = 2^18
    const int s = v & (SPAT - 1);
    const int z = s >> 12;

    const float* st = state + (size_t)b * NCH * SPAT;
    float* ot = out + (size_t)b * NCH * SPAT;

    float e    = st[0 * SPAT + s];
    float anch = st[1 * SPAT + s];
    float pos = (z >= 3) ? 1.f : anch;
    float legal = fminf(fmaxf((1.f - e) * pos, 0.f), 1.f);
    float avail = 1.f - e;

    // frozen channels pass through
    ot[0 * SPAT + s] = e;
    ot[1 * SPAT + s] = anch;
    ot[2 * SPAT + s] = st[2 * SPAT + s];
    ot[3 * SPAT + s] = st[3 * SPAT + s];

    // structural channel (grown j=0) with masking
    {
        float d0 = acc[0] + b3[0];
        float g0 = fminf(fmaxf(st[4 * SPAT + s] + 0.1f * d0, 0.f), 1.f);
        ot[4 * SPAT + s] = g0 * avail * legal;
    }
#pragma unroll
    for (int j = 1; j < 12; ++j) {
        float d = acc[j] + b3[j];
        float g = fminf(fmaxf(st[(4 + j) * SPAT + s] + 0.1f * d, 0.f), 1.f);
        ot[(4 + j) * SPAT + s] = g;
    }
}

// ---------------------------------------------------------------------------
extern "C" void kernel_launch(void* const* d_in, const int* in_sizes, int n_in,
                              void* d_out, int out_size) {
    const float* state = (const float*)d_in[0];
    const float* w1 = (const float*)d_in[1];
    const float* b1 = (const float*)d_in[2];
    const float* w2 = (const float*)d_in[3];
    const float* b2 = (const float*)d_in[4];
    const float* w3 = (const float*)d_in[5];
    const float* b3 = (const float*)d_in[6];
    float* out = (float*)d_out;

    // 1) transpose weights into channel-major form
    k_transpose<<<32, 256>>>(w1, w2);

    // 2) perceive -> g_bufA rows 0..63 (channel-major)
    dim3 pb(8, 8, 8);
    dim3 pg(GDIM / 8, GDIM / 8, (GDIM / 8) * BATCH);
    k_perceive<<<pg, pb>>>(state);

    // 3) h1 = relu(perc @ W1^T + b1) -> g_bufB
    k_gemm<64><<<NTOT / 64, 256>>>(b1);

    // 4) h2 = relu(h1 @ W2^T + b2) -> g_bufA
    k_gemm<128><<<NTOT / 64, 256>>>(b2);

    // 5) delta = h2 @ W3^T + b3, fused NCA masking epilogue -> out
    k_final<<<NTOT / 256, 256>>>(w3, b3, state, out);
}

// round 4
// speedup vs baseline: 1.8021x; 1.8021x over previous
#include <cuda_runtime.h>
#include <cuda_bf16.h>
#include <cstdint>

// Problem constants
#define GDIM   64
#define SPAT   (GDIM*GDIM*GDIM)      // 262144 voxels per batch
#define BATCH  2
#define NTOT   (BATCH*SPAT)          // 524288 total voxels
#define NCH    16
#define HID    128
#define NGROWN 12

// Scratch (static __device__; referenced ONLY from device code — passing these
// from host passes the ATS-readable host shadow => silent zeros on GB300).
__device__ __align__(256) __nv_bfloat16 g_perc[64u * (unsigned)NTOT];
__device__ __align__(256) __nv_bfloat16 g_h1[128u * (unsigned)NTOT];
__device__ __align__(256) __nv_bfloat16 g_h2[128u * (unsigned)NTOT];
__device__ __align__(256) __nv_bfloat16 g_w1b[128 * 64];    // [o][k] bf16
__device__ __align__(256) __nv_bfloat16 g_w2b[128 * 128];   // [o][k] bf16

__device__ __forceinline__ uint32_t smem_u32(const void* p) {
    return (uint32_t)__cvta_generic_to_shared(p);
}

#define MMA_BF16(C, A, B0, B1)                                               \
    asm volatile(                                                            \
        "mma.sync.aligned.m16n8k16.row.col.f32.bf16.bf16.f32 "               \
        "{%0,%1,%2,%3},{%4,%5,%6,%7},{%8,%9},{%0,%1,%2,%3};"                 \
        : "+f"((C)[0]), "+f"((C)[1]), "+f"((C)[2]), "+f"((C)[3])             \
        : "r"((A)[0]), "r"((A)[1]), "r"((A)[2]), "r"((A)[3]),                \
          "r"(B0), "r"(B1))

// ---------------------------------------------------------------------------
// Weight convert fp32 -> bf16 (keeps original [o][k] layout)
// ---------------------------------------------------------------------------
__global__ void k_convert(const float* __restrict__ w1,
                          const float* __restrict__ w2) {
    int tid = blockIdx.x * blockDim.x + threadIdx.x;
    int stride = gridDim.x * blockDim.x;
    for (int i = tid; i < 128 * 64; i += stride)
        g_w1b[i] = __float2bfloat16(w1[i]);
    for (int i = tid; i < 128 * 128; i += stride)
        g_w2b[i] = __float2bfloat16(w2[i]);
}

// ---------------------------------------------------------------------------
// Perceive: depthwise [identity, sobel_x, sobel_y, sobel_z], edge-clamped.
// fp32 math, bf16 channel-major output into g_perc.
// ---------------------------------------------------------------------------
__global__ void k_perceive(const float* __restrict__ state) {
    __shared__ float t[10][10][10];
    const int lx = threadIdx.x, ly = threadIdx.y, lz = threadIdx.z;
    const int tid = (lz * 8 + ly) * 8 + lx;
    const int x0 = blockIdx.x * 8;
    const int y0 = blockIdx.y * 8;
    const int b  = blockIdx.z >> 3;
    const int z0 = (blockIdx.z & 7) * 8;
    const int gx = x0 + lx, gy = y0 + ly, gz = z0 + lz;
    const int sidx = (gz << 12) + (gy << 6) + gx;
    const int v = b * SPAT + sidx;
    const float s3[3] = {1.f, 2.f, 1.f};

    for (int c = 0; c < NCH; ++c) {
        const float* sc = state + (size_t)(b * NCH + c) * SPAT;
        for (int i = tid; i < 1000; i += 512) {
            int iz = i / 100;
            int iy = (i / 10) % 10;
            int ix = i % 10;
            int cz = min(max(z0 + iz - 1, 0), GDIM - 1);
            int cy = min(max(y0 + iy - 1, 0), GDIM - 1);
            int cx = min(max(x0 + ix - 1, 0), GDIM - 1);
            t[iz][iy][ix] = sc[(cz << 12) + (cy << 6) + cx];
        }
        __syncthreads();

        float ident = t[lz + 1][ly + 1][lx + 1];
        float sx = 0.f, sy = 0.f, sz = 0.f;
#pragma unroll
        for (int a = 0; a < 3; ++a) {
#pragma unroll
            for (int bb = 0; bb < 3; ++bb) {
                float r0 = t[lz + a][ly + bb][lx + 0];
                float r1 = t[lz + a][ly + bb][lx + 1];
                float r2 = t[lz + a][ly + bb][lx + 2];
                float sum = r0 + 2.f * r1 + r2;
                sx += (s3[a] * s3[bb]) * (r2 - r0);
                sy += (s3[a] * (float)(bb - 1)) * sum;
                sz += ((float)(a - 1) * s3[bb]) * sum;
            }
        }
        sx *= (1.f / 16.f); sy *= (1.f / 16.f); sz *= (1.f / 16.f);

        g_perc[(0 * NCH + c) * NTOT + v] = __float2bfloat16(ident);
        g_perc[(1 * NCH + c) * NTOT + v] = __float2bfloat16(sx);
        g_perc[(2 * NCH + c) * NTOT + v] = __float2bfloat16(sy);
        g_perc[(3 * NCH + c) * NTOT + v] = __float2bfloat16(sz);
        __syncthreads();
    }
}

// ---------------------------------------------------------------------------
// bf16 tensor-core GEMM + bias + ReLU (mma.sync m16n8k16, fp32 accumulate).
//   C[o][v] = relu(sum_k W[o][k] * A[k][v] + bias[o]),  o = 0..127
// Block tile: 128 outputs x 128 voxels, 8 warps (warp w -> o rows w*16..+15).
// Weights loaded directly from global into A-fragment layout (registers).
// Activations staged in padded smem, loaded with ldmatrix.x4.trans.
// ---------------------------------------------------------------------------
template <int K>
__global__ void __launch_bounds__(256) k_gemm_mma(const float* __restrict__ bias) {
    const __nv_bfloat16* Asrc = (K == 64) ? g_perc : g_h1;
    const __nv_bfloat16* Wsrc = (K == 64) ? g_w1b : g_w2b;
    __nv_bfloat16*       Cdst = (K == 64) ? g_h1  : g_h2;

    // Overlay: sA[k][136] during compute (K*136 elems), sOut[128][136] in epilogue.
    __shared__ __align__(16) __nv_bfloat16 smem[128 * 136];

    const int tid  = threadIdx.x;
    const int warp = tid >> 5;
    const int lane = tid & 31;
    const int vbase = blockIdx.x * 128;

    // Stage activations: K rows x 128 voxels (16B chunks), padded stride 136.
    for (int c = tid; c < K * 16; c += 256) {
        int row = c >> 4, col = c & 15;
        *(uint4*)&smem[row * 136 + col * 8] =
            *(const uint4*)&Asrc[(size_t)row * NTOT + vbase + col * 8];
    }

    // Weight A-fragments straight from global (L2-resident, frag layout).
    constexpr int NKS = K / 16;
    uint32_t aw[NKS][4];
    const int m0 = warp * 16 + (lane >> 2);
    const int kq = (lane & 3) * 2;
#pragma unroll
    for (int ks = 0; ks < NKS; ++ks) {
        int kb = ks * 16 + kq;
        aw[ks][0] = *(const uint32_t*)&Wsrc[m0 * K + kb];
        aw[ks][1] = *(const uint32_t*)&Wsrc[(m0 + 8) * K + kb];
        aw[ks][2] = *(const uint32_t*)&Wsrc[m0 * K + kb + 8];
        aw[ks][3] = *(const uint32_t*)&Wsrc[(m0 + 8) * K + kb + 8];
    }
    __syncthreads();

    float acc[16][4];
#pragma unroll
    for (int nt = 0; nt < 16; ++nt)
#pragma unroll
        for (int i = 0; i < 4; ++i) acc[nt][i] = 0.f;

    const int brow  = lane & 15;
    const int bcolh = (lane >> 4) * 8;
#pragma unroll
    for (int ks = 0; ks < NKS; ++ks) {
#pragma unroll
        for (int ntp = 0; ntp < 8; ++ntp) {
            uint32_t addr = smem_u32(
                &smem[(ks * 16 + brow) * 136 + ntp * 16 + bcolh]);
            uint32_t b0, b1, b2, b3;
            asm volatile(
                "ldmatrix.sync.aligned.m8n8.x4.trans.shared.b16 "
                "{%0,%1,%2,%3}, [%4];"
                : "=r"(b0), "=r"(b1), "=r"(b2), "=r"(b3) : "r"(addr));
            MMA_BF16(acc[2 * ntp],     aw[ks], b0, b1);
            MMA_BF16(acc[2 * ntp + 1], aw[ks], b2, b3);
        }
    }
    __syncthreads();

    // Epilogue: bias + relu + bf16 pack into smem, then coalesced store.
    const float bm  = bias[warp * 16 + (lane >> 2)];
    const float bm8 = bias[warp * 16 + (lane >> 2) + 8];
    const int erow0 = (warp * 16 + (lane >> 2)) * 136;
    const int erow1 = erow0 + 8 * 136;
#pragma unroll
    for (int nt = 0; nt < 16; ++nt) {
        int ncol = nt * 8 + (lane & 3) * 2;
        __nv_bfloat162 p0 = __floats2bfloat162_rn(
            fmaxf(acc[nt][0] + bm, 0.f), fmaxf(acc[nt][1] + bm, 0.f));
        __nv_bfloat162 p1 = __floats2bfloat162_rn(
            fmaxf(acc[nt][2] + bm8, 0.f), fmaxf(acc[nt][3] + bm8, 0.f));
        *(__nv_bfloat162*)&smem[erow0 + ncol] = p0;
        *(__nv_bfloat162*)&smem[erow1 + ncol] = p1;
    }
    __syncthreads();

    for (int c = tid; c < 128 * 16; c += 256) {
        int row = c >> 4, col = c & 15;
        *(uint4*)&Cdst[(size_t)row * NTOT + vbase + col * 8] =
            *(const uint4*)&smem[row * 136 + col * 8];
    }
}

// ---------------------------------------------------------------------------
// Final: GEMM3 (128 -> 12) + NCA update epilogue. h2 read from g_h2 (bf16),
// 2 voxels per thread, fp32 accumulate.
// ---------------------------------------------------------------------------
__global__ void __launch_bounds__(256) k_final(const float* __restrict__ w3,
                                               const float* __restrict__ b3,
                                               const float* __restrict__ state,
                                               float* __restrict__ out) {
    __shared__ float sW[128 * 12];   // sW[k][j] = w3[j][k]
    const int tid = threadIdx.x;
    for (int i = tid; i < 128 * 12; i += 256) {
        int k = i / 12;
        int j = i - k * 12;
        sW[k * 12 + j] = w3[j * 128 + k];
    }
    __syncthreads();

    const int v0 = (blockIdx.x * 256 + tid) * 2;

    float acc[12][2];
#pragma unroll
    for (int j = 0; j < 12; ++j) { acc[j][0] = 0.f; acc[j][1] = 0.f; }

#pragma unroll 4
    for (int k = 0; k < 128; ++k) {
        __nv_bfloat162 hv = *(const __nv_bfloat162*)&g_h2[(size_t)k * NTOT + v0];
        float x0 = __bfloat162float(hv.x);
        float x1 = __bfloat162float(hv.y);
        const float4* wr = (const float4*)&sW[k * 12];
        float4 w0 = wr[0], w1v = wr[1], w2v = wr[2];
        acc[0][0] += x0 * w0.x;  acc[0][1] += x1 * w0.x;
        acc[1][0] += x0 * w0.y;  acc[1][1] += x1 * w0.y;
        acc[2][0] += x0 * w0.z;  acc[2][1] += x1 * w0.z;
        acc[3][0] += x0 * w0.w;  acc[3][1] += x1 * w0.w;
        acc[4][0] += x0 * w1v.x; acc[4][1] += x1 * w1v.x;
        acc[5][0] += x0 * w1v.y; acc[5][1] += x1 * w1v.y;
        acc[6][0] += x0 * w1v.z; acc[6][1] += x1 * w1v.z;
        acc[7][0] += x0 * w1v.w; acc[7][1] += x1 * w1v.w;
        acc[8][0] += x0 * w2v.x; acc[8][1] += x1 * w2v.x;
        acc[9][0] += x0 * w2v.y; acc[9][1] += x1 * w2v.y;
        acc[10][0] += x0 * w2v.z; acc[10][1] += x1 * w2v.z;
        acc[11][0] += x0 * w2v.w; acc[11][1] += x1 * w2v.w;
    }

    const int b = v0 >> 18;            // SPAT = 2^18
    const int s = v0 & (SPAT - 1);     // even
    const int z = s >> 12;             // identical for s and s+1 (s even)

    const float* st = state + (size_t)b * NCH * SPAT;
    float* ot = out + (size_t)b * NCH * SPAT;

    float2 e2  = *(const float2*)&st[0 * SPAT + s];
    float2 an2 = *(const float2*)&st[1 * SPAT + s];

    float pos0 = (z >= 3) ? 1.f : an2.x;
    float pos1 = (z >= 3) ? 1.f : an2.y;
    float legal0 = fminf(fmaxf((1.f - e2.x) * pos0, 0.f), 1.f);
    float legal1 = fminf(fmaxf((1.f - e2.y) * pos1, 0.f), 1.f);
    float avail0 = 1.f - e2.x;
    float avail1 = 1.f - e2.y;

    // frozen channels pass through
    *(float2*)&ot[0 * SPAT + s] = e2;
    *(float2*)&ot[1 * SPAT + s] = an2;
    *(float2*)&ot[2 * SPAT + s] = *(const float2*)&st[2 * SPAT + s];
    *(float2*)&ot[3 * SPAT + s] = *(const float2*)&st[3 * SPAT + s];

    // structural channel (grown j=0) with masking
    {
        float bj = b3[0];
        float2 sv = *(const float2*)&st[4 * SPAT + s];
        float g0 = fminf(fmaxf(sv.x + 0.1f * (acc[0][0] + bj), 0.f), 1.f);
        float g1 = fminf(fmaxf(sv.y + 0.1f * (acc[0][1] + bj), 0.f), 1.f);
        float2 r; r.x = g0 * avail0 * legal0; r.y = g1 * avail1 * legal1;
        *(float2*)&ot[4 * SPAT + s] = r;
    }
#pragma unroll
    for (int j = 1; j < 12; ++j) {
        float bj = b3[j];
        float2 sv = *(const float2*)&st[(4 + j) * SPAT + s];
        float2 r;
        r.x = fminf(fmaxf(sv.x + 0.1f * (acc[j][0] + bj), 0.f), 1.f);
        r.y = fminf(fmaxf(sv.y + 0.1f * (acc[j][1] + bj), 0.f), 1.f);
        *(float2*)&ot[(4 + j) * SPAT + s] = r;
    }
}

// ---------------------------------------------------------------------------
extern "C" void kernel_launch(void* const* d_in, const int* in_sizes, int n_in,
                              void* d_out, int out_size) {
    const float* state = (const float*)d_in[0];
    const float* w1 = (const float*)d_in[1];
    const float* b1 = (const float*)d_in[2];
    const float* w2 = (const float*)d_in[3];
    const float* b2 = (const float*)d_in[4];
    const float* w3 = (const float*)d_in[5];
    const float* b3 = (const float*)d_in[6];
    float* out = (float*)d_out;

    // 1) weights fp32 -> bf16 ([o][k] layout kept)
    k_convert<<<24, 256>>>(w1, w2);

    // 2) perceive -> g_perc (64 ch, bf16, channel-major)
    dim3 pb(8, 8, 8);
    dim3 pg(GDIM / 8, GDIM / 8, (GDIM / 8) * BATCH);
    k_perceive<<<pg, pb>>>(state);

    // 3) h1 = relu(W1 @ perc + b1) -> g_h1   (bf16 tensor cores)
    k_gemm_mma<64><<<NTOT / 128, 256>>>(b1);

    // 4) h2 = relu(W2 @ h1 + b2) -> g_h2
    k_gemm_mma<128><<<NTOT / 128, 256>>>(b2);

    // 5) delta = W3 @ h2 + b3, fused NCA masking epilogue -> out
    k_final<<<NTOT / 512, 256>>>(w3, b3, state, out);
}

// round 5
// speedup vs baseline: 2.3448x; 1.3012x over previous
#include <cuda_runtime.h>
#include <cuda_bf16.h>
#include <cstdint>

// Problem constants
#define GDIM   64
#define SPAT   (GDIM*GDIM*GDIM)      // 262144 voxels per batch
#define BATCH  2
#define NTOT   (BATCH*SPAT)          // 524288 total voxels
#define NCH    16

// Scratch (static __device__; referenced ONLY from device code — host-side use
// of these symbols passes the ATS-readable host shadow => silent zeros).
__device__ __align__(256) __nv_bfloat16 g_perc[64u * (unsigned)NTOT];
__device__ __align__(256) __nv_bfloat16 g_w1b[128 * 64];    // [o][k]
__device__ __align__(256) __nv_bfloat16 g_w2b[128 * 128];   // [o][k]
__device__ __align__(256) __nv_bfloat16 g_w3b[16 * 128];    // [o][k], rows 12..15 zero

__device__ __forceinline__ uint32_t smem_u32(const void* p) {
    return (uint32_t)__cvta_generic_to_shared(p);
}

#define MMA_BF16(C, A, B0, B1)                                               \
    asm volatile(                                                            \
        "mma.sync.aligned.m16n8k16.row.col.f32.bf16.bf16.f32 "               \
        "{%0,%1,%2,%3},{%4,%5,%6,%7},{%8,%9},{%0,%1,%2,%3};"                 \
        : "+f"((C)[0]), "+f"((C)[1]), "+f"((C)[2]), "+f"((C)[3])             \
        : "r"((A)[0]), "r"((A)[1]), "r"((A)[2]), "r"((A)[3]),                \
          "r"(B0), "r"(B1))

#define LDMX4T(B0, B1, B2, B3, ADDR)                                         \
    asm volatile(                                                            \
        "ldmatrix.sync.aligned.m8n8.x4.trans.shared.b16 {%0,%1,%2,%3},[%4];" \
        : "=r"(B0), "=r"(B1), "=r"(B2), "=r"(B3) : "r"(ADDR))

// ---------------------------------------------------------------------------
// Weight convert fp32 -> bf16 (w3 zero-padded to 16 output rows)
// ---------------------------------------------------------------------------
__global__ void k_convert(const float* __restrict__ w1,
                          const float* __restrict__ w2,
                          const float* __restrict__ w3) {
    int tid = blockIdx.x * blockDim.x + threadIdx.x;
    int stride = gridDim.x * blockDim.x;
    for (int i = tid; i < 128 * 64; i += stride)
        g_w1b[i] = __float2bfloat16(w1[i]);
    for (int i = tid; i < 128 * 128; i += stride)
        g_w2b[i] = __float2bfloat16(w2[i]);
    for (int i = tid; i < 16 * 128; i += stride) {
        int row = i >> 7;
        g_w3b[i] = (row < 12) ? __float2bfloat16(w3[i]) : __float2bfloat16(0.f);
    }
}

// ---------------------------------------------------------------------------
// Perceive: depthwise [identity, sobel_x, sobel_y, sobel_z], edge-clamped.
// fp32 math, bf16 channel-major output into g_perc.
// ---------------------------------------------------------------------------
__global__ void k_perceive(const float* __restrict__ state) {
    __shared__ float t[10][10][10];
    const int lx = threadIdx.x, ly = threadIdx.y, lz = threadIdx.z;
    const int tid = (lz * 8 + ly) * 8 + lx;
    const int x0 = blockIdx.x * 8;
    const int y0 = blockIdx.y * 8;
    const int b  = blockIdx.z >> 3;
    const int z0 = (blockIdx.z & 7) * 8;
    const int gx = x0 + lx, gy = y0 + ly, gz = z0 + lz;
    const int sidx = (gz << 12) + (gy << 6) + gx;
    const int v = b * SPAT + sidx;
    const float s3[3] = {1.f, 2.f, 1.f};

    for (int c = 0; c < NCH; ++c) {
        const float* sc = state + (size_t)(b * NCH + c) * SPAT;
        for (int i = tid; i < 1000; i += 512) {
            int iz = i / 100;
            int iy = (i / 10) % 10;
            int ix = i % 10;
            int cz = min(max(z0 + iz - 1, 0), GDIM - 1);
            int cy = min(max(y0 + iy - 1, 0), GDIM - 1);
            int cx = min(max(x0 + ix - 1, 0), GDIM - 1);
            t[iz][iy][ix] = sc[(cz << 12) + (cy << 6) + cx];
        }
        __syncthreads();

        float ident = t[lz + 1][ly + 1][lx + 1];
        float sx = 0.f, sy = 0.f, sz = 0.f;
#pragma unroll
        for (int a = 0; a < 3; ++a) {
#pragma unroll
            for (int bb = 0; bb < 3; ++bb) {
                float r0 = t[lz + a][ly + bb][lx + 0];
                float r1 = t[lz + a][ly + bb][lx + 1];
                float r2 = t[lz + a][ly + bb][lx + 2];
                float sum = r0 + 2.f * r1 + r2;
                sx += (s3[a] * s3[bb]) * (r2 - r0);
                sy += (s3[a] * (float)(bb - 1)) * sum;
                sz += ((float)(a - 1) * s3[bb]) * sum;
            }
        }
        sx *= (1.f / 16.f); sy *= (1.f / 16.f); sz *= (1.f / 16.f);

        g_perc[(0 * NCH + c) * NTOT + v] = __float2bfloat16(ident);
        g_perc[(1 * NCH + c) * NTOT + v] = __float2bfloat16(sx);
        g_perc[(2 * NCH + c) * NTOT + v] = __float2bfloat16(sy);
        g_perc[(3 * NCH + c) * NTOT + v] = __float2bfloat16(sz);
        __syncthreads();
    }
}

// ---------------------------------------------------------------------------
// Fused MLP: perc -> h1 -> h2 -> delta -> NCA epilogue, one 64-voxel tile per
// block, everything flowing through shared memory. 256 threads, 8 warps.
//   gemm1: warp w -> h1 rows w*16..+15 (K=64),  64 voxel cols
//   gemm2: warp w -> h2 rows w*16..+15 (K=128)
//   gemm3: warps 0..3, 16 padded output rows (12 real), warp w -> cols w*16..+15
// ---------------------------------------------------------------------------
__global__ void __launch_bounds__(256, 2)
k_mlp(const float* __restrict__ b1,
      const float* __restrict__ b2,
      const float* __restrict__ b3,
      const float* __restrict__ state,
      float* __restrict__ out) {
    __shared__ __align__(16) __nv_bfloat16 sP[64 * 72];    // perc tile; later delta (fp32 overlay)
    __shared__ __align__(16) __nv_bfloat16 sH1[128 * 72];
    __shared__ __align__(16) __nv_bfloat16 sH2[128 * 72];
    float* sD = (float*)sP;   // 12 x 68 fp32 = 3264B  (< 9216B, perc dead by then)

    const int tid  = threadIdx.x;
    const int warp = tid >> 5;
    const int lane = tid & 31;
    const int vbase = blockIdx.x * 64;

    const int m0  = warp * 16 + (lane >> 2);
    const int kq  = (lane & 3) * 2;
    const int brow = lane & 15;
    const int bch  = (lane >> 4) * 8;

    // ---- stage perc tile (64 rows x 64 cols) ----
    for (int c = tid; c < 64 * 8; c += 256) {
        int row = c >> 3, col = c & 7;
        *(uint4*)&sP[row * 72 + col * 8] =
            *(const uint4*)&g_perc[(size_t)row * NTOT + vbase + col * 8];
    }

    // W1 fragments (K=64): 4 k-steps
    uint32_t aw1[4][4];
#pragma unroll
    for (int ks = 0; ks < 4; ++ks) {
        int kb = ks * 16 + kq;
        aw1[ks][0] = *(const uint32_t*)&g_w1b[m0 * 64 + kb];
        aw1[ks][1] = *(const uint32_t*)&g_w1b[(m0 + 8) * 64 + kb];
        aw1[ks][2] = *(const uint32_t*)&g_w1b[m0 * 64 + kb + 8];
        aw1[ks][3] = *(const uint32_t*)&g_w1b[(m0 + 8) * 64 + kb + 8];
    }
    __syncthreads();

    // ---- gemm1: h1 = relu(W1 @ perc + b1) ----
    float acc[8][4];
#pragma unroll
    for (int nt = 0; nt < 8; ++nt)
#pragma unroll
        for (int i = 0; i < 4; ++i) acc[nt][i] = 0.f;

#pragma unroll
    for (int ks = 0; ks < 4; ++ks) {
#pragma unroll
        for (int ntp = 0; ntp < 4; ++ntp) {
            uint32_t addr = smem_u32(&sP[(ks * 16 + brow) * 72 + ntp * 16 + bch]);
            uint32_t b0, b1r, b2r, b3r;
            LDMX4T(b0, b1r, b2r, b3r, addr);
            MMA_BF16(acc[2 * ntp],     aw1[ks], b0, b1r);
            MMA_BF16(acc[2 * ntp + 1], aw1[ks], b2r, b3r);
        }
    }
    {
        const float bm  = b1[m0];
        const float bm8 = b1[m0 + 8];
#pragma unroll
        for (int nt = 0; nt < 8; ++nt) {
            int ncol = nt * 8 + (lane & 3) * 2;
            *(__nv_bfloat162*)&sH1[m0 * 72 + ncol] = __floats2bfloat162_rn(
                fmaxf(acc[nt][0] + bm, 0.f), fmaxf(acc[nt][1] + bm, 0.f));
            *(__nv_bfloat162*)&sH1[(m0 + 8) * 72 + ncol] = __floats2bfloat162_rn(
                fmaxf(acc[nt][2] + bm8, 0.f), fmaxf(acc[nt][3] + bm8, 0.f));
        }
    }

    // W2 fragments (K=128): 8 k-steps — loads overlap the barrier
    uint32_t aw2[8][4];
#pragma unroll
    for (int ks = 0; ks < 8; ++ks) {
        int kb = ks * 16 + kq;
        aw2[ks][0] = *(const uint32_t*)&g_w2b[m0 * 128 + kb];
        aw2[ks][1] = *(const uint32_t*)&g_w2b[(m0 + 8) * 128 + kb];
        aw2[ks][2] = *(const uint32_t*)&g_w2b[m0 * 128 + kb + 8];
        aw2[ks][3] = *(const uint32_t*)&g_w2b[(m0 + 8) * 128 + kb + 8];
    }
    __syncthreads();

    // ---- gemm2: h2 = relu(W2 @ h1 + b2) ----
#pragma unroll
    for (int nt = 0; nt < 8; ++nt)
#pragma unroll
        for (int i = 0; i < 4; ++i) acc[nt][i] = 0.f;

#pragma unroll
    for (int ks = 0; ks < 8; ++ks) {
#pragma unroll
        for (int ntp = 0; ntp < 4; ++ntp) {
            uint32_t addr = smem_u32(&sH1[(ks * 16 + brow) * 72 + ntp * 16 + bch]);
            uint32_t b0, b1r, b2r, b3r;
            LDMX4T(b0, b1r, b2r, b3r, addr);
            MMA_BF16(acc[2 * ntp],     aw2[ks], b0, b1r);
            MMA_BF16(acc[2 * ntp + 1], aw2[ks], b2r, b3r);
        }
    }
    {
        const float bm  = b2[m0];
        const float bm8 = b2[m0 + 8];
#pragma unroll
        for (int nt = 0; nt < 8; ++nt) {
            int ncol = nt * 8 + (lane & 3) * 2;
            *(__nv_bfloat162*)&sH2[m0 * 72 + ncol] = __floats2bfloat162_rn(
                fmaxf(acc[nt][0] + bm, 0.f), fmaxf(acc[nt][1] + bm, 0.f));
            *(__nv_bfloat162*)&sH2[(m0 + 8) * 72 + ncol] = __floats2bfloat162_rn(
                fmaxf(acc[nt][2] + bm8, 0.f), fmaxf(acc[nt][3] + bm8, 0.f));
        }
    }
    __syncthreads();

    // ---- gemm3: delta = W3 @ h2  (bias added in epilogue) ----
    if (warp < 4) {
        // W3 fragments: 16 padded rows, rows 12..15 zero
        const int w3m = lane >> 2;
        uint32_t aw3[8][4];
#pragma unroll
        for (int ks = 0; ks < 8; ++ks) {
            int kb = ks * 16 + kq;
            aw3[ks][0] = *(const uint32_t*)&g_w3b[w3m * 128 + kb];
            aw3[ks][1] = *(const uint32_t*)&g_w3b[(w3m + 8) * 128 + kb];
            aw3[ks][2] = *(const uint32_t*)&g_w3b[w3m * 128 + kb + 8];
            aw3[ks][3] = *(const uint32_t*)&g_w3b[(w3m + 8) * 128 + kb + 8];
        }
        float acc3[2][4];
#pragma unroll
        for (int nt = 0; nt < 2; ++nt)
#pragma unroll
            for (int i = 0; i < 4; ++i) acc3[nt][i] = 0.f;

#pragma unroll
        for (int ks = 0; ks < 8; ++ks) {
            uint32_t addr = smem_u32(&sH2[(ks * 16 + brow) * 72 + warp * 16 + bch]);
            uint32_t b0, b1r, b2r, b3r;
            LDMX4T(b0, b1r, b2r, b3r, addr);
            MMA_BF16(acc3[0], aw3[ks], b0, b1r);
            MMA_BF16(acc3[1], aw3[ks], b2r, b3r);
        }
#pragma unroll
        for (int nt = 0; nt < 2; ++nt) {
            int col = warp * 16 + nt * 8 + (lane & 3) * 2;
            sD[w3m * 68 + col]     = acc3[nt][0];
            sD[w3m * 68 + col + 1] = acc3[nt][1];
            if (w3m + 8 < 12) {
                sD[(w3m + 8) * 68 + col]     = acc3[nt][2];
                sD[(w3m + 8) * 68 + col + 1] = acc3[nt][3];
            }
        }
    }
    __syncthreads();

    // ---- NCA epilogue ----
    const int v   = tid & 63;
    const int grp = tid >> 6;          // 0..3 -> channels grp*4..grp*4+3
    const int vG  = vbase + v;
    const int b   = vG >> 18;          // SPAT = 2^18
    const int s   = vG & (SPAT - 1);
    const int z   = s >> 12;

    const float* st = state + (size_t)b * NCH * SPAT;
    float* ot = out + (size_t)b * NCH * SPAT;

    if (grp == 0) {
#pragma unroll
        for (int ch = 0; ch < 4; ++ch)
            ot[ch * SPAT + s] = st[ch * SPAT + s];
    } else {
        float e = 0.f, legal = 0.f;
        if (grp == 1) {
            e = st[s];
            float anch = st[SPAT + s];
            float pos = (z >= 3) ? 1.f : anch;
            legal = fminf(fmaxf((1.f - e) * pos, 0.f), 1.f);
        }
        const int j0 = (grp - 1) * 4;
#pragma unroll
        for (int jj = 0; jj < 4; ++jj) {
            int j = j0 + jj;
            float d = sD[j * 68 + v] + b3[j];
            float g = fminf(fmaxf(st[(4 + j) * SPAT + s] + 0.1f * d, 0.f), 1.f);
            if (grp == 1 && jj == 0) g = g * (1.f - e) * legal;
            ot[(4 + j) * SPAT + s] = g;
        }
    }
}

// ---------------------------------------------------------------------------
extern "C" void kernel_launch(void* const* d_in, const int* in_sizes, int n_in,
                              void* d_out, int out_size) {
    const float* state = (const float*)d_in[0];
    const float* w1 = (const float*)d_in[1];
    const float* b1 = (const float*)d_in[2];
    const float* w2 = (const float*)d_in[3];
    const float* b2 = (const float*)d_in[4];
    const float* w3 = (const float*)d_in[5];
    const float* b3 = (const float*)d_in[6];
    float* out = (float*)d_out;

    // 1) weights fp32 -> bf16
    k_convert<<<24, 256>>>(w1, w2, w3);

    // 2) perceive -> g_perc (64 ch, bf16, channel-major)
    dim3 pb(8, 8, 8);
    dim3 pg(GDIM / 8, GDIM / 8, (GDIM / 8) * BATCH);
    k_perceive<<<pg, pb>>>(state);

    // 3) fused MLP + epilogue
    k_mlp<<<NTOT / 64, 256>>>(b1, b2, b3, state, out);
}

// round 6
// speedup vs baseline: 2.3588x; 1.0060x over previous
#include <cuda_runtime.h>
#include <cuda_bf16.h>
#include <cstdint>

// Problem constants
#define GDIM   64
#define SPAT   (GDIM*GDIM*GDIM)      // 262144 voxels per batch
#define BATCH  2
#define NTOT   (BATCH*SPAT)          // 524288 total voxels
#define NCH    16

// Weights, bf16 (static __device__; referenced ONLY from device code — using
// these symbols on the host passes the ATS-readable host shadow => zeros).
__device__ __align__(256) __nv_bfloat16 g_w1b[128 * 64];    // [o][k]
__device__ __align__(256) __nv_bfloat16 g_w2b[128 * 128];   // [o][k]
__device__ __align__(256) __nv_bfloat16 g_w3b[16 * 128];    // [o][k], rows 12..15 zero

__device__ __forceinline__ uint32_t smem_u32(const void* p) {
    return (uint32_t)__cvta_generic_to_shared(p);
}

#define MMA_BF16(C, A, B0, B1)                                               \
    asm volatile(                                                            \
        "mma.sync.aligned.m16n8k16.row.col.f32.bf16.bf16.f32 "               \
        "{%0,%1,%2,%3},{%4,%5,%6,%7},{%8,%9},{%0,%1,%2,%3};"                 \
        : "+f"((C)[0]), "+f"((C)[1]), "+f"((C)[2]), "+f"((C)[3])             \
        : "r"((A)[0]), "r"((A)[1]), "r"((A)[2]), "r"((A)[3]),                \
          "r"(B0), "r"(B1))

#define LDMX4T(B0, B1, B2, B3, ADDR)                                         \
    asm volatile(                                                            \
        "ldmatrix.sync.aligned.m8n8.x4.trans.shared.b16 {%0,%1,%2,%3},[%4];" \
        : "=r"(B0), "=r"(B1), "=r"(B2), "=r"(B3) : "r"(ADDR))

// ---------------------------------------------------------------------------
// Weight convert fp32 -> bf16 (w3 zero-padded to 16 output rows)
// ---------------------------------------------------------------------------
__global__ void k_convert(const float* __restrict__ w1,
                          const float* __restrict__ w2,
                          const float* __restrict__ w3) {
    int tid = blockIdx.x * blockDim.x + threadIdx.x;
    int stride = gridDim.x * blockDim.x;
    for (int i = tid; i < 128 * 64; i += stride)
        g_w1b[i] = __float2bfloat16(w1[i]);
    for (int i = tid; i < 128 * 128; i += stride)
        g_w2b[i] = __float2bfloat16(w2[i]);
    for (int i = tid; i < 16 * 128; i += stride) {
        int row = i >> 7;
        g_w3b[i] = (row < 12) ? __float2bfloat16(w3[i]) : __float2bfloat16(0.f);
    }
}

// ---------------------------------------------------------------------------
// Fully fused NCA step: perceive (in-smem) -> gemm1 -> gemm2 -> gemm3 -> NCA
// epilogue. One block = one x-row of 64 voxels (b, z, y fixed).
// 256 threads, 8 warps. Smem overlays (46080 B static):
//   phase A: sState 16ch x 9 rows x 64 fp32 (36864 B) | sP 64x72 bf16 (9216 B)
//   phase B: sH1 (18432) + sH2 (18432) overlay sState; sD overlays sP.
// ---------------------------------------------------------------------------
__global__ void __launch_bounds__(256, 2)
k_fused(const float* __restrict__ state,
        const float* __restrict__ b1,
        const float* __restrict__ b2,
        const float* __restrict__ b3,
        float* __restrict__ out) {
    __shared__ __align__(16) char uSmem[46080];
    float*         sS  = (float*)uSmem;                       // 16*9*64 fp32
    __nv_bfloat16* sH1 = (__nv_bfloat16*)uSmem;               // 128*72 bf16
    __nv_bfloat16* sH2 = (__nv_bfloat16*)(uSmem + 18432);     // 128*72 bf16
    __nv_bfloat16* sP  = (__nv_bfloat16*)(uSmem + 36864);     // 64*72 bf16
    float*         sD  = (float*)(uSmem + 36864);             // 12*68 fp32

    const int tid  = threadIdx.x;
    const int warp = tid >> 5;
    const int lane = tid & 31;

    const int bid = blockIdx.x;            // 0..8191
    const int b   = bid >> 12;
    const int z   = (bid >> 6) & 63;
    const int y   = bid & 63;
    const int vbase = bid * 64;            // linear == b*SPAT + z*4096 + y*64

    // ---- load state halo: 16 ch x 3(dz) x 3(dy) clamped x-rows ----
    {
        const float* stb = state + ((size_t)b << 18) * NCH;
#pragma unroll 4
        for (int i = tid; i < 144 * 64; i += 256) {
            int r = i >> 6, x = i & 63;
            int ch  = r / 9;
            int rem = r - ch * 9;
            int dzi = rem / 3;
            int dyi = rem - dzi * 3;
            int cz = min(max(z + dzi - 1, 0), 63);
            int cy = min(max(y + dyi - 1, 0), 63);
            sS[r * 64 + x] = stb[((size_t)ch << 18) + (cz << 12) + (cy << 6) + x];
        }
    }

    // W1 fragments (K=64): 4 k-steps — global loads overlap the barrier
    const int m0  = warp * 16 + (lane >> 2);
    const int kq  = (lane & 3) * 2;
    const int brow = lane & 15;
    const int bch  = (lane >> 4) * 8;

    uint32_t aw1[4][4];
#pragma unroll
    for (int ks = 0; ks < 4; ++ks) {
        int kb = ks * 16 + kq;
        aw1[ks][0] = *(const uint32_t*)&g_w1b[m0 * 64 + kb];
        aw1[ks][1] = *(const uint32_t*)&g_w1b[(m0 + 8) * 64 + kb];
        aw1[ks][2] = *(const uint32_t*)&g_w1b[m0 * 64 + kb + 8];
        aw1[ks][3] = *(const uint32_t*)&g_w1b[(m0 + 8) * 64 + kb + 8];
    }
    __syncthreads();

    // ---- perceive stencil: 4 (ch,x) pairs per thread -> sP (bf16) ----
    {
        const float s3[3] = {1.f, 2.f, 1.f};
#pragma unroll
        for (int p = 0; p < 4; ++p) {
            int idx = tid + p * 256;       // 0..1023
            int ch = idx >> 6, x = idx & 63;
            int xm = max(x - 1, 0), xp = min(x + 1, 63);
            const float* base = sS + ch * 576;
            float ident = base[4 * 64 + x];     // (dz=1,dy=1)
            float sx = 0.f, sy = 0.f, sz = 0.f;
#pragma unroll
            for (int a = 0; a < 3; ++a) {
#pragma unroll
                for (int bb = 0; bb < 3; ++bb) {
                    const float* row = base + (a * 3 + bb) * 64;
                    float r0 = row[xm], r1 = row[x], r2 = row[xp];
                    float sum = r0 + 2.f * r1 + r2;
                    sx += (s3[a] * s3[bb]) * (r2 - r0);
                    sy += (s3[a] * (float)(bb - 1)) * sum;
                    sz += ((float)(a - 1) * s3[bb]) * sum;
                }
            }
            sP[(0 * 16 + ch) * 72 + x] = __float2bfloat16(ident);
            sP[(1 * 16 + ch) * 72 + x] = __float2bfloat16(sx * (1.f / 16.f));
            sP[(2 * 16 + ch) * 72 + x] = __float2bfloat16(sy * (1.f / 16.f));
            sP[(3 * 16 + ch) * 72 + x] = __float2bfloat16(sz * (1.f / 16.f));
        }
    }
    __syncthreads();   // sP ready; sState now dead -> sH1/sH2 may overwrite

    // ---- gemm1: h1 = relu(W1 @ perc + b1) ----
    float acc[8][4];
#pragma unroll
    for (int nt = 0; nt < 8; ++nt)
#pragma unroll
        for (int i = 0; i < 4; ++i) acc[nt][i] = 0.f;

#pragma unroll
    for (int ks = 0; ks < 4; ++ks) {
#pragma unroll
        for (int ntp = 0; ntp < 4; ++ntp) {
            uint32_t addr = smem_u32(&sP[(ks * 16 + brow) * 72 + ntp * 16 + bch]);
            uint32_t b0, b1r, b2r, b3r;
            LDMX4T(b0, b1r, b2r, b3r, addr);
            MMA_BF16(acc[2 * ntp],     aw1[ks], b0, b1r);
            MMA_BF16(acc[2 * ntp + 1], aw1[ks], b2r, b3r);
        }
    }
    {
        const float bm  = b1[m0];
        const float bm8 = b1[m0 + 8];
#pragma unroll
        for (int nt = 0; nt < 8; ++nt) {
            int ncol = nt * 8 + (lane & 3) * 2;
            *(__nv_bfloat162*)&sH1[m0 * 72 + ncol] = __floats2bfloat162_rn(
                fmaxf(acc[nt][0] + bm, 0.f), fmaxf(acc[nt][1] + bm, 0.f));
            *(__nv_bfloat162*)&sH1[(m0 + 8) * 72 + ncol] = __floats2bfloat162_rn(
                fmaxf(acc[nt][2] + bm8, 0.f), fmaxf(acc[nt][3] + bm8, 0.f));
        }
    }

    // W2 fragments (K=128): 8 k-steps — loads overlap the barrier
    uint32_t aw2[8][4];
#pragma unroll
    for (int ks = 0; ks < 8; ++ks) {
        int kb = ks * 16 + kq;
        aw2[ks][0] = *(const uint32_t*)&g_w2b[m0 * 128 + kb];
        aw2[ks][1] = *(const uint32_t*)&g_w2b[(m0 + 8) * 128 + kb];
        aw2[ks][2] = *(const uint32_t*)&g_w2b[m0 * 128 + kb + 8];
        aw2[ks][3] = *(const uint32_t*)&g_w2b[(m0 + 8) * 128 + kb + 8];
    }
    __syncthreads();

    // ---- gemm2: h2 = relu(W2 @ h1 + b2) ----
#pragma unroll
    for (int nt = 0; nt < 8; ++nt)
#pragma unroll
        for (int i = 0; i < 4; ++i) acc[nt][i] = 0.f;

#pragma unroll
    for (int ks = 0; ks < 8; ++ks) {
#pragma unroll
        for (int ntp = 0; ntp < 4; ++ntp) {
            uint32_t addr = smem_u32(&sH1[(ks * 16 + brow) * 72 + ntp * 16 + bch]);
            uint32_t b0, b1r, b2r, b3r;
            LDMX4T(b0, b1r, b2r, b3r, addr);
            MMA_BF16(acc[2 * ntp],     aw2[ks], b0, b1r);
            MMA_BF16(acc[2 * ntp + 1], aw2[ks], b2r, b3r);
        }
    }
    {
        const float bm  = b2[m0];
        const float bm8 = b2[m0 + 8];
#pragma unroll
        for (int nt = 0; nt < 8; ++nt) {
            int ncol = nt * 8 + (lane & 3) * 2;
            *(__nv_bfloat162*)&sH2[m0 * 72 + ncol] = __floats2bfloat162_rn(
                fmaxf(acc[nt][0] + bm, 0.f), fmaxf(acc[nt][1] + bm, 0.f));
            *(__nv_bfloat162*)&sH2[(m0 + 8) * 72 + ncol] = __floats2bfloat162_rn(
                fmaxf(acc[nt][2] + bm8, 0.f), fmaxf(acc[nt][3] + bm8, 0.f));
        }
    }
    __syncthreads();

    // ---- gemm3: delta = W3 @ h2 (bias added in epilogue) ----
    if (warp < 4) {
        const int w3m = lane >> 2;
        uint32_t aw3[8][4];
#pragma unroll
        for (int ks = 0; ks < 8; ++ks) {
            int kb = ks * 16 + kq;
            aw3[ks][0] = *(const uint32_t*)&g_w3b[w3m * 128 + kb];
            aw3[ks][1] = *(const uint32_t*)&g_w3b[(w3m + 8) * 128 + kb];
            aw3[ks][2] = *(const uint32_t*)&g_w3b[w3m * 128 + kb + 8];
            aw3[ks][3] = *(const uint32_t*)&g_w3b[(w3m + 8) * 128 + kb + 8];
        }
        float acc3[2][4];
#pragma unroll
        for (int nt = 0; nt < 2; ++nt)
#pragma unroll
            for (int i = 0; i < 4; ++i) acc3[nt][i] = 0.f;

#pragma unroll
        for (int ks = 0; ks < 8; ++ks) {
            uint32_t addr = smem_u32(&sH2[(ks * 16 + brow) * 72 + warp * 16 + bch]);
            uint32_t b0, b1r, b2r, b3r;
            LDMX4T(b0, b1r, b2r, b3r, addr);
            MMA_BF16(acc3[0], aw3[ks], b0, b1r);
            MMA_BF16(acc3[1], aw3[ks], b2r, b3r);
        }
#pragma unroll
        for (int nt = 0; nt < 2; ++nt) {
            int col = warp * 16 + nt * 8 + (lane & 3) * 2;
            sD[w3m * 68 + col]     = acc3[nt][0];
            sD[w3m * 68 + col + 1] = acc3[nt][1];
            if (w3m + 8 < 12) {
                sD[(w3m + 8) * 68 + col]     = acc3[nt][2];
                sD[(w3m + 8) * 68 + col + 1] = acc3[nt][3];
            }
        }
    }
    __syncthreads();

    // ---- NCA epilogue ----
    const int v   = tid & 63;
    const int grp = tid >> 6;          // 0..3 -> channels grp*4..grp*4+3
    const int vG  = vbase + v;
    const int s   = vG & (SPAT - 1);

    const float* st = state + (size_t)b * NCH * SPAT;
    float* ot = out + (size_t)b * NCH * SPAT;

    if (grp == 0) {
#pragma unroll
        for (int ch = 0; ch < 4; ++ch)
            ot[ch * SPAT + s] = st[ch * SPAT + s];
    } else {
        float e = 0.f, legal = 0.f;
        if (grp == 1) {
            e = st[s];
            float anch = st[SPAT + s];
            float pos = (z >= 3) ? 1.f : anch;
            legal = fminf(fmaxf((1.f - e) * pos, 0.f), 1.f);
        }
        const int j0 = (grp - 1) * 4;
#pragma unroll
        for (int jj = 0; jj < 4; ++jj) {
            int j = j0 + jj;
            float d = sD[j * 68 + v] + b3[j];
            float g = fminf(fmaxf(st[(4 + j) * SPAT + s] + 0.1f * d, 0.f), 1.f);
            if (grp == 1 && jj == 0) g = g * (1.f - e) * legal;
            ot[(4 + j) * SPAT + s] = g;
        }
    }
}

// ---------------------------------------------------------------------------
extern "C" void kernel_launch(void* const* d_in, const int* in_sizes, int n_in,
                              void* d_out, int out_size) {
    const float* state = (const float*)d_in[0];
    const float* w1 = (const float*)d_in[1];
    const float* b1 = (const float*)d_in[2];
    const float* w2 = (const float*)d_in[3];
    const float* b2 = (const float*)d_in[4];
    const float* w3 = (const float*)d_in[5];
    const float* b3 = (const float*)d_in[6];
    float* out = (float*)d_out;

    // 1) weights fp32 -> bf16
    k_convert<<<96, 256>>>(w1, w2, w3);

    // 2) fused perceive + MLP + epilogue (one block per x-row)
    k_fused<<<NTOT / 64, 256>>>(state, b1, b2, b3, out);
}

// round 7
// speedup vs baseline: 3.1647x; 1.3416x over previous
#include <cuda_runtime.h>
#include <cuda_bf16.h>
#include <cstdint>

// Problem constants
#define GDIM   64
#define SPAT   (GDIM*GDIM*GDIM)      // 262144 voxels per batch
#define BATCH  2
#define NTOT   (BATCH*SPAT)          // 524288 total voxels
#define NCH    16

// Weights, bf16 (static __device__; referenced ONLY from device code — using
// these symbols on the host passes the ATS-readable host shadow => zeros).
__device__ __align__(256) __nv_bfloat16 g_w1b[128 * 64];    // [o][k]
__device__ __align__(256) __nv_bfloat16 g_w2b[128 * 128];   // [o][k]
__device__ __align__(256) __nv_bfloat16 g_w3b[16 * 128];    // [o][k], rows 12..15 zero

__device__ __forceinline__ uint32_t smem_u32(const void* p) {
    return (uint32_t)__cvta_generic_to_shared(p);
}

#define MMA_BF16(C, A, B0, B1)                                               \
    asm volatile(                                                            \
        "mma.sync.aligned.m16n8k16.row.col.f32.bf16.bf16.f32 "               \
        "{%0,%1,%2,%3},{%4,%5,%6,%7},{%8,%9},{%0,%1,%2,%3};"                 \
        : "+f"((C)[0]), "+f"((C)[1]), "+f"((C)[2]), "+f"((C)[3])             \
        : "r"((A)[0]), "r"((A)[1]), "r"((A)[2]), "r"((A)[3]),                \
          "r"(B0), "r"(B1))

#define LDMX4T(B0, B1, B2, B3, ADDR)                                         \
    asm volatile(                                                            \
        "ldmatrix.sync.aligned.m8n8.x4.trans.shared.b16 {%0,%1,%2,%3},[%4];" \
        : "=r"(B0), "=r"(B1), "=r"(B2), "=r"(B3) : "r"(ADDR))

// Load one 16x16 A-fragment (4 regs) for row m0r, k-offset kb, row stride Kk.
#define LDW(dst, basep, Kk, m0r, kb)                                          \
    do {                                                                      \
        (dst)[0] = *(const uint32_t*)&(basep)[(m0r) * (Kk) + (kb)];           \
        (dst)[1] = *(const uint32_t*)&(basep)[((m0r) + 8) * (Kk) + (kb)];     \
        (dst)[2] = *(const uint32_t*)&(basep)[(m0r) * (Kk) + (kb) + 8];       \
        (dst)[3] = *(const uint32_t*)&(basep)[((m0r) + 8) * (Kk) + (kb) + 8]; \
    } while (0)

// ---------------------------------------------------------------------------
// Weight convert fp32 -> bf16 (w3 zero-padded to 16 output rows)
// ---------------------------------------------------------------------------
__global__ void k_convert(const float* __restrict__ w1,
                          const float* __restrict__ w2,
                          const float* __restrict__ w3) {
    int tid = blockIdx.x * blockDim.x + threadIdx.x;
    int stride = gridDim.x * blockDim.x;
    for (int i = tid; i < 128 * 64; i += stride)
        g_w1b[i] = __float2bfloat16(w1[i]);
    for (int i = tid; i < 128 * 128; i += stride)
        g_w2b[i] = __float2bfloat16(w2[i]);
    for (int i = tid; i < 16 * 128; i += stride) {
        int row = i >> 7;
        g_w3b[i] = (row < 12) ? __float2bfloat16(w3[i]) : __float2bfloat16(0.f);
    }
}

// ---------------------------------------------------------------------------
// Fully fused NCA step. One block = one x-row of 64 voxels.
// Smem (48384 B static):
//   phase A: sS [9 rows][16 ch][68 pad] fp32 (39168 B) | sP 64x72 bf16 (9216 B)
//   phase B: sH1 (18432) + sH2 (18432) overlay sS; sD (3264 fp32) overlays sP.
// ---------------------------------------------------------------------------
__global__ void __launch_bounds__(256, 3)
k_fused(const float* __restrict__ state,
        const float* __restrict__ b1,
        const float* __restrict__ b2,
        const float* __restrict__ b3,
        float* __restrict__ out) {
    __shared__ __align__(16) char uSmem[48384];
    float*         sS  = (float*)uSmem;                       // 9*1088 fp32
    __nv_bfloat16* sH1 = (__nv_bfloat16*)uSmem;               // 128*72 bf16
    __nv_bfloat16* sH2 = (__nv_bfloat16*)(uSmem + 18432);     // 128*72 bf16
    __nv_bfloat16* sP  = (__nv_bfloat16*)(uSmem + 39168);     // 64*72 bf16
    float*         sD  = (float*)(uSmem + 39168);             // 12*68 fp32

    const int tid  = threadIdx.x;
    const int warp = tid >> 5;
    const int lane = tid & 31;

    const int bid = blockIdx.x;            // 0..8191
    const int b   = bid >> 12;
    const int z   = (bid >> 6) & 63;
    const int y   = bid & 63;
    const int vbase = bid * 64;

    // ---- halo load: 9 rows (dz,dy const per unrolled iter) x 16ch x 64x ----
    {
        const float* stb = state + (((size_t)b * NCH) << 18);
        const int ch = tid >> 4;
        const int x4 = (tid & 15) * 4;
        const size_t gbase = ((size_t)ch << 18) + x4;
#pragma unroll
        for (int it = 0; it < 9; ++it) {
            const int dzi = it / 3, dyi = it % 3;    // compile-time constants
            int cz = min(max(z + dzi - 1, 0), 63);
            int cy = min(max(y + dyi - 1, 0), 63);
            *(float4*)&sS[it * 1088 + ch * 68 + x4] =
                *(const float4*)&stb[gbase + (cz << 12) + (cy << 6)];
        }
    }
    __syncthreads();

    // ---- perceive stencil: separable sums, 4 consecutive x per thread ----
    {
        const float WS[9]  = {1, 2, 1, 2, 4, 2, 1, 2, 1};
        const float WDY[9] = {-1, 0, 1, -2, 0, 2, -1, 0, 1};
        const float WDZ[9] = {-1, -2, -1, 0, 0, 0, 1, 2, 1};
        const int ch = tid >> 4;
        const int xq = (tid & 15) * 4;
        const int xl = max(xq - 1, 0);
        const int xr = min(xq + 4, 63);

        float S[6], DY[6], DZ[6], id4[4];
#pragma unroll
        for (int j = 0; j < 6; ++j) { S[j] = 0.f; DY[j] = 0.f; DZ[j] = 0.f; }

#pragma unroll
        for (int r = 0; r < 9; ++r) {
            const float* row = sS + r * 1088 + ch * 68;
            float4 v4 = *(const float4*)&row[xq];
            float v[6] = {row[xl], v4.x, v4.y, v4.z, v4.w, row[xr]};
            if (r == 4) { id4[0] = v[1]; id4[1] = v[2]; id4[2] = v[3]; id4[3] = v[4]; }
#pragma unroll
            for (int j = 0; j < 6; ++j) {
                S[j] += WS[r] * v[j];
                if (WDY[r] != 0.f) DY[j] += WDY[r] * v[j];
                if (WDZ[r] != 0.f) DZ[j] += WDZ[r] * v[j];
            }
        }

        float ox[4], oy[4], oz[4];
#pragma unroll
        for (int i = 0; i < 4; ++i) {
            ox[i] = (S[i + 2] - S[i]) * (1.f / 16.f);
            oy[i] = (DY[i] + 2.f * DY[i + 1] + DY[i + 2]) * (1.f / 16.f);
            oz[i] = (DZ[i] + 2.f * DZ[i + 1] + DZ[i + 2]) * (1.f / 16.f);
        }
        __nv_bfloat162* p;
        p = (__nv_bfloat162*)&sP[(0 * 16 + ch) * 72 + xq];
        p[0] = __floats2bfloat162_rn(id4[0], id4[1]);
        p[1] = __floats2bfloat162_rn(id4[2], id4[3]);
        p = (__nv_bfloat162*)&sP[(1 * 16 + ch) * 72 + xq];
        p[0] = __floats2bfloat162_rn(ox[0], ox[1]);
        p[1] = __floats2bfloat162_rn(ox[2], ox[3]);
        p = (__nv_bfloat162*)&sP[(2 * 16 + ch) * 72 + xq];
        p[0] = __floats2bfloat162_rn(oy[0], oy[1]);
        p[1] = __floats2bfloat162_rn(oy[2], oy[3]);
        p = (__nv_bfloat162*)&sP[(3 * 16 + ch) * 72 + xq];
        p[0] = __floats2bfloat162_rn(oz[0], oz[1]);
        p[1] = __floats2bfloat162_rn(oz[2], oz[3]);
    }
    __syncthreads();   // sP ready; sS dead -> sH1/sH2 may overwrite

    const int m0   = warp * 16 + (lane >> 2);
    const int kq   = (lane & 3) * 2;
    const int brow = lane & 15;
    const int bch  = (lane >> 4) * 8;

    float acc[8][4];
    uint32_t awc[4], awn[4];

    // ---- gemm1: h1 = relu(W1 @ perc + b1) ---- (weights streamed per k-step)
#pragma unroll
    for (int nt = 0; nt < 8; ++nt)
#pragma unroll
        for (int i = 0; i < 4; ++i) acc[nt][i] = 0.f;

    LDW(awc, g_w1b, 64, m0, kq);
#pragma unroll
    for (int ks = 0; ks < 4; ++ks) {
        if (ks < 3) LDW(awn, g_w1b, 64, m0, (ks + 1) * 16 + kq);
#pragma unroll
        for (int ntp = 0; ntp < 4; ++ntp) {
            uint32_t addr = smem_u32(&sP[(ks * 16 + brow) * 72 + ntp * 16 + bch]);
            uint32_t b0, b1r, b2r, b3r;
            LDMX4T(b0, b1r, b2r, b3r, addr);
            MMA_BF16(acc[2 * ntp],     awc, b0, b1r);
            MMA_BF16(acc[2 * ntp + 1], awc, b2r, b3r);
        }
#pragma unroll
        for (int i = 0; i < 4; ++i) awc[i] = awn[i];
    }
    {
        const float bm  = b1[m0];
        const float bm8 = b1[m0 + 8];
#pragma unroll
        for (int nt = 0; nt < 8; ++nt) {
            int ncol = nt * 8 + (lane & 3) * 2;
            *(__nv_bfloat162*)&sH1[m0 * 72 + ncol] = __floats2bfloat162_rn(
                fmaxf(acc[nt][0] + bm, 0.f), fmaxf(acc[nt][1] + bm, 0.f));
            *(__nv_bfloat162*)&sH1[(m0 + 8) * 72 + ncol] = __floats2bfloat162_rn(
                fmaxf(acc[nt][2] + bm8, 0.f), fmaxf(acc[nt][3] + bm8, 0.f));
        }
    }
    __syncthreads();

    // ---- gemm2: h2 = relu(W2 @ h1 + b2) ----
#pragma unroll
    for (int nt = 0; nt < 8; ++nt)
#pragma unroll
        for (int i = 0; i < 4; ++i) acc[nt][i] = 0.f;

    LDW(awc, g_w2b, 128, m0, kq);
#pragma unroll
    for (int ks = 0; ks < 8; ++ks) {
        if (ks < 7) LDW(awn, g_w2b, 128, m0, (ks + 1) * 16 + kq);
#pragma unroll
        for (int ntp = 0; ntp < 4; ++ntp) {
            uint32_t addr = smem_u32(&sH1[(ks * 16 + brow) * 72 + ntp * 16 + bch]);
            uint32_t b0, b1r, b2r, b3r;
            LDMX4T(b0, b1r, b2r, b3r, addr);
            MMA_BF16(acc[2 * ntp],     awc, b0, b1r);
            MMA_BF16(acc[2 * ntp + 1], awc, b2r, b3r);
        }
#pragma unroll
        for (int i = 0; i < 4; ++i) awc[i] = awn[i];
    }
    {
        const float bm  = b2[m0];
        const float bm8 = b2[m0 + 8];
#pragma unroll
        for (int nt = 0; nt < 8; ++nt) {
            int ncol = nt * 8 + (lane & 3) * 2;
            *(__nv_bfloat162*)&sH2[m0 * 72 + ncol] = __floats2bfloat162_rn(
                fmaxf(acc[nt][0] + bm, 0.f), fmaxf(acc[nt][1] + bm, 0.f));
            *(__nv_bfloat162*)&sH2[(m0 + 8) * 72 + ncol] = __floats2bfloat162_rn(
                fmaxf(acc[nt][2] + bm8, 0.f), fmaxf(acc[nt][3] + bm8, 0.f));
        }
    }
    __syncthreads();

    // ---- gemm3: delta = W3 @ h2 (bias added in epilogue) ----
    if (warp < 4) {
        const int w3m = lane >> 2;
        float acc3[2][4];
#pragma unroll
        for (int nt = 0; nt < 2; ++nt)
#pragma unroll
            for (int i = 0; i < 4; ++i) acc3[nt][i] = 0.f;

        LDW(awc, g_w3b, 128, w3m, kq);
#pragma unroll
        for (int ks = 0; ks < 8; ++ks) {
            if (ks < 7) LDW(awn, g_w3b, 128, w3m, (ks + 1) * 16 + kq);
            uint32_t addr = smem_u32(&sH2[(ks * 16 + brow) * 72 + warp * 16 + bch]);
            uint32_t b0, b1r, b2r, b3r;
            LDMX4T(b0, b1r, b2r, b3r, addr);
            MMA_BF16(acc3[0], awc, b0, b1r);
            MMA_BF16(acc3[1], awc, b2r, b3r);
#pragma unroll
            for (int i = 0; i < 4; ++i) awc[i] = awn[i];
        }
#pragma unroll
        for (int nt = 0; nt < 2; ++nt) {
            int col = warp * 16 + nt * 8 + (lane & 3) * 2;
            sD[w3m * 68 + col]     = acc3[nt][0];
            sD[w3m * 68 + col + 1] = acc3[nt][1];
            if (w3m + 8 < 12) {
                sD[(w3m + 8) * 68 + col]     = acc3[nt][2];
                sD[(w3m + 8) * 68 + col + 1] = acc3[nt][3];
            }
        }
    }
    __syncthreads();

    // ---- NCA epilogue ----
    const int v   = tid & 63;
    const int grp = tid >> 6;          // 0..3 -> channels grp*4..grp*4+3
    const int vG  = vbase + v;
    const int s   = vG & (SPAT - 1);

    const float* st = state + (size_t)b * NCH * SPAT;
    float* ot = out + (size_t)b * NCH * SPAT;

    if (grp == 0) {
#pragma unroll
        for (int ch = 0; ch < 4; ++ch)
            ot[ch * SPAT + s] = st[ch * SPAT + s];
    } else {
        float e = 0.f, legal = 0.f;
        if (grp == 1) {
            e = st[s];
            float anch = st[SPAT + s];
            float pos = (z >= 3) ? 1.f : anch;
            legal = fminf(fmaxf((1.f - e) * pos, 0.f), 1.f);
        }
        const int j0 = (grp - 1) * 4;
#pragma unroll
        for (int jj = 0; jj < 4; ++jj) {
            int j = j0 + jj;
            float d = sD[j * 68 + v] + b3[j];
            float g = fminf(fmaxf(st[(4 + j) * SPAT + s] + 0.1f * d, 0.f), 1.f);
            if (grp == 1 && jj == 0) g = g * (1.f - e) * legal;
            ot[(4 + j) * SPAT + s] = g;
        }
    }
}

// ---------------------------------------------------------------------------
extern "C" void kernel_launch(void* const* d_in, const int* in_sizes, int n_in,
                              void* d_out, int out_size) {
    const float* state = (const float*)d_in[0];
    const float* w1 = (const float*)d_in[1];
    const float* b1 = (const float*)d_in[2];
    const float* w2 = (const float*)d_in[3];
    const float* b2 = (const float*)d_in[4];
    const float* w3 = (const float*)d_in[5];
    const float* b3 = (const float*)d_in[6];
    float* out = (float*)d_out;

    // 1) weights fp32 -> bf16
    k_convert<<<96, 256>>>(w1, w2, w3);

    // 2) fused perceive + MLP + epilogue (one block per x-row)
    k_fused<<<NTOT / 64, 256>>>(state, b1, b2, b3, out);
}

// round 8
// speedup vs baseline: 3.8701x; 1.2229x over previous
#include <cuda_runtime.h>
#include <cuda_bf16.h>
#include <cstdint>

// Problem constants
#define GDIM   64
#define SPAT   (GDIM*GDIM*GDIM)      // 262144 voxels per batch
#define BATCH  2
#define NTOT   (BATCH*SPAT)          // 524288 total voxels
#define NCH    16

// Weights, bf16 (static __device__; referenced ONLY from device code — using
// these symbols on the host passes the ATS-readable host shadow => zeros).
__device__ __align__(256) __nv_bfloat16 g_w1b[128 * 64];    // [o][k]
__device__ __align__(256) __nv_bfloat16 g_w2b[128 * 128];   // [o][k]
__device__ __align__(256) __nv_bfloat16 g_w3b[16 * 128];    // [o][k], rows 12..15 zero

__device__ __forceinline__ uint32_t smem_u32(const void* p) {
    return (uint32_t)__cvta_generic_to_shared(p);
}

#define MMA_BF16(C, A, B0, B1)                                               \
    asm volatile(                                                            \
        "mma.sync.aligned.m16n8k16.row.col.f32.bf16.bf16.f32 "               \
        "{%0,%1,%2,%3},{%4,%5,%6,%7},{%8,%9},{%0,%1,%2,%3};"                 \
        : "+f"((C)[0]), "+f"((C)[1]), "+f"((C)[2]), "+f"((C)[3])             \
        : "r"((A)[0]), "r"((A)[1]), "r"((A)[2]), "r"((A)[3]),                \
          "r"(B0), "r"(B1))

#define LDMX4T(B0, B1, B2, B3, ADDR)                                         \
    asm volatile(                                                            \
        "ldmatrix.sync.aligned.m8n8.x4.trans.shared.b16 {%0,%1,%2,%3},[%4];" \
        : "=r"(B0), "=r"(B1), "=r"(B2), "=r"(B3) : "r"(ADDR))

// Load one 16x16 A-fragment (4 regs) for row m0r, k-offset kb, row stride Kk.
#define LDW(dst, basep, Kk, m0r, kb)                                          \
    do {                                                                      \
        (dst)[0] = *(const uint32_t*)&(basep)[(m0r) * (Kk) + (kb)];           \
        (dst)[1] = *(const uint32_t*)&(basep)[((m0r) + 8) * (Kk) + (kb)];     \
        (dst)[2] = *(const uint32_t*)&(basep)[(m0r) * (Kk) + (kb) + 8];       \
        (dst)[3] = *(const uint32_t*)&(basep)[((m0r) + 8) * (Kk) + (kb) + 8]; \
    } while (0)

// Smem layout (dynamic, 87040 B):
//   [0      .. 34816)  sH1  128 x 136 bf16
//   [34816  .. 69632)  sH2  128 x 136 bf16
//   [69632  .. 87040)  sP   64 x 136 bf16   (gemm1 input; dead after gemm1)
//   [69632  .. 76000)  sD   12 x 132 fp32   (overlays sP, written in gemm3)
#define SMEM_BYTES 87040

// ---------------------------------------------------------------------------
// Weight convert fp32 -> bf16 (w3 zero-padded to 16 output rows)
// ---------------------------------------------------------------------------
__global__ void k_convert(const float* __restrict__ w1,
                          const float* __restrict__ w2,
                          const float* __restrict__ w3) {
    int tid = blockIdx.x * blockDim.x + threadIdx.x;
    int stride = gridDim.x * blockDim.x;
    for (int i = tid; i < 128 * 64; i += stride)
        g_w1b[i] = __float2bfloat16(w1[i]);
    for (int i = tid; i < 128 * 128; i += stride)
        g_w2b[i] = __float2bfloat16(w2[i]);
    for (int i = tid; i < 16 * 128; i += stride) {
        int row = i >> 7;
        g_w3b[i] = (row < 12) ? __float2bfloat16(w3[i]) : __float2bfloat16(0.f);
    }
}

// ---------------------------------------------------------------------------
// Fully fused NCA step. One block = 128 voxels (two consecutive x-rows:
// y0, y0+1 at fixed b,z). 256 threads, 8 warps, warp grid 4(M) x 2(N).
// ---------------------------------------------------------------------------
__global__ void __launch_bounds__(256, 2)
k_fused(const float* __restrict__ state,
        const float* __restrict__ b1,
        const float* __restrict__ b2,
        const float* __restrict__ b3,
        float* __restrict__ out) {
    extern __shared__ __align__(16) char uSmem[];
    __nv_bfloat16* sH1 = (__nv_bfloat16*)uSmem;               // 128*136
    __nv_bfloat16* sH2 = (__nv_bfloat16*)(uSmem + 34816);     // 128*136
    __nv_bfloat16* sP  = (__nv_bfloat16*)(uSmem + 69632);     // 64*136
    float*         sD  = (float*)(uSmem + 69632);             // 12*132

    const int tid  = threadIdx.x;
    const int warp = tid >> 5;
    const int lane = tid & 31;

    const int bid = blockIdx.x;            // 0..4095
    const int b   = bid >> 11;
    const int z   = (bid >> 5) & 63;
    const int y0  = (bid & 31) * 2;
    const int vbase = bid * 128;           // linear voxel base

    // ---- perceive stencil: direct LDG + warp shuffles (no smem staging) ----
    // task = (yi, ch, xqi): 2 tasks/thread; warp = same yi, 2 ch x 16 xqi.
    {
        const float WS[9]  = {1, 2, 1, 2, 4, 2, 1, 2, 1};
        const float WDY[9] = {-1, 0, 1, -2, 0, 2, -1, 0, 1};
        const float WDZ[9] = {-1, -2, -1, 0, 0, 0, 1, 2, 1};
        const int xqi = tid & 15;
        const int ch  = (tid >> 4) & 15;
        const int xq  = xqi * 4;
        const float* chbase = state + (((size_t)(b * NCH + ch)) << 18) + xq;

#pragma unroll
        for (int t = 0; t < 2; ++t) {
            const int yi = t;
            const int y  = y0 + yi;

            float S[6], DY[6], DZ[6], id4[4];
#pragma unroll
            for (int j = 0; j < 6; ++j) { S[j] = 0.f; DY[j] = 0.f; DZ[j] = 0.f; }

#pragma unroll
            for (int a = 0; a < 3; ++a) {
                int cz = min(max(z + a - 1, 0), 63);
#pragma unroll
                for (int bb = 0; bb < 3; ++bb) {
                    int cy = min(max(y + bb - 1, 0), 63);
                    int r = a * 3 + bb;
                    float4 v4 = *(const float4*)&chbase[(cz << 12) + (cy << 6)];
                    // x-neighbors via shuffle (x-1 from lane-1's .w, x+4 from lane+1's .x)
                    float xl = __shfl_up_sync(0xFFFFFFFFu, v4.w, 1);
                    float xr = __shfl_down_sync(0xFFFFFFFFu, v4.x, 1);
                    if (xqi == 0)  xl = v4.x;   // clamp at x=0
                    if (xqi == 15) xr = v4.w;   // clamp at x=63
                    float v[6] = {xl, v4.x, v4.y, v4.z, v4.w, xr};
                    if (r == 4) { id4[0] = v[1]; id4[1] = v[2]; id4[2] = v[3]; id4[3] = v[4]; }
#pragma unroll
                    for (int j = 0; j < 6; ++j) {
                        S[j] += WS[r] * v[j];
                        if (WDY[r] != 0.f) DY[j] += WDY[r] * v[j];
                        if (WDZ[r] != 0.f) DZ[j] += WDZ[r] * v[j];
                    }
                }
            }

            float ox[4], oy[4], oz[4];
#pragma unroll
            for (int i = 0; i < 4; ++i) {
                ox[i] = (S[i + 2] - S[i]) * (1.f / 16.f);
                oy[i] = (DY[i] + 2.f * DY[i + 1] + DY[i + 2]) * (1.f / 16.f);
                oz[i] = (DZ[i] + 2.f * DZ[i + 1] + DZ[i + 2]) * (1.f / 16.f);
            }
            const int col = yi * 64 + xq;
            __nv_bfloat162* p;
            p = (__nv_bfloat162*)&sP[(0 * 16 + ch) * 136 + col];
            p[0] = __floats2bfloat162_rn(id4[0], id4[1]);
            p[1] = __floats2bfloat162_rn(id4[2], id4[3]);
            p = (__nv_bfloat162*)&sP[(1 * 16 + ch) * 136 + col];
            p[0] = __floats2bfloat162_rn(ox[0], ox[1]);
            p[1] = __floats2bfloat162_rn(ox[2], ox[3]);
            p = (__nv_bfloat162*)&sP[(2 * 16 + ch) * 136 + col];
            p[0] = __floats2bfloat162_rn(oy[0], oy[1]);
            p[1] = __floats2bfloat162_rn(oy[2], oy[3]);
            p = (__nv_bfloat162*)&sP[(3 * 16 + ch) * 136 + col];
            p[0] = __floats2bfloat162_rn(oz[0], oz[1]);
            p[1] = __floats2bfloat162_rn(oz[2], oz[3]);
        }
    }
    __syncthreads();

    // warp tiling: 4(M) x 2(N); warp tile = 32 out-rows x 64 voxel-cols
    const int wm   = warp >> 1;
    const int wn   = warp & 1;
    const int mrow = (lane >> 2);          // 0..7
    const int m0   = wm * 32 + mrow;
    const int kq   = (lane & 3) * 2;
    const int brow = lane & 15;
    const int bch  = (lane >> 4) * 8;

    float acc[2][8][4];
    uint32_t aw0[4], aw1[4];

    // ---- gemm1: h1 = relu(W1 @ perc + b1), K=64 ----
#pragma unroll
    for (int mi = 0; mi < 2; ++mi)
#pragma unroll
        for (int nt = 0; nt < 8; ++nt)
#pragma unroll
            for (int i = 0; i < 4; ++i) acc[mi][nt][i] = 0.f;

#pragma unroll
    for (int ks = 0; ks < 4; ++ks) {
        LDW(aw0, g_w1b, 64, m0, ks * 16 + kq);
        LDW(aw1, g_w1b, 64, m0 + 16, ks * 16 + kq);
#pragma unroll
        for (int ntp = 0; ntp < 4; ++ntp) {
            uint32_t addr = smem_u32(&sP[(ks * 16 + brow) * 136 + wn * 64 + ntp * 16 + bch]);
            uint32_t b0r, b1r, b2r, b3r;
            LDMX4T(b0r, b1r, b2r, b3r, addr);
            MMA_BF16(acc[0][2 * ntp],     aw0, b0r, b1r);
            MMA_BF16(acc[0][2 * ntp + 1], aw0, b2r, b3r);
            MMA_BF16(acc[1][2 * ntp],     aw1, b0r, b1r);
            MMA_BF16(acc[1][2 * ntp + 1], aw1, b2r, b3r);
        }
    }
#pragma unroll
    for (int mi = 0; mi < 2; ++mi) {
        const int rm = wm * 32 + mi * 16 + mrow;
        const float bm  = b1[rm];
        const float bm8 = b1[rm + 8];
#pragma unroll
        for (int nt = 0; nt < 8; ++nt) {
            int col = wn * 64 + nt * 8 + (lane & 3) * 2;
            *(__nv_bfloat162*)&sH1[rm * 136 + col] = __floats2bfloat162_rn(
                fmaxf(acc[mi][nt][0] + bm, 0.f), fmaxf(acc[mi][nt][1] + bm, 0.f));
            *(__nv_bfloat162*)&sH1[(rm + 8) * 136 + col] = __floats2bfloat162_rn(
                fmaxf(acc[mi][nt][2] + bm8, 0.f), fmaxf(acc[mi][nt][3] + bm8, 0.f));
        }
    }
    __syncthreads();

    // ---- gemm2: h2 = relu(W2 @ h1 + b2), K=128 ----
#pragma unroll
    for (int mi = 0; mi < 2; ++mi)
#pragma unroll
        for (int nt = 0; nt < 8; ++nt)
#pragma unroll
            for (int i = 0; i < 4; ++i) acc[mi][nt][i] = 0.f;

#pragma unroll
    for (int ks = 0; ks < 8; ++ks) {
        LDW(aw0, g_w2b, 128, m0, ks * 16 + kq);
        LDW(aw1, g_w2b, 128, m0 + 16, ks * 16 + kq);
#pragma unroll
        for (int ntp = 0; ntp < 4; ++ntp) {
            uint32_t addr = smem_u32(&sH1[(ks * 16 + brow) * 136 + wn * 64 + ntp * 16 + bch]);
            uint32_t b0r, b1r, b2r, b3r;
            LDMX4T(b0r, b1r, b2r, b3r, addr);
            MMA_BF16(acc[0][2 * ntp],     aw0, b0r, b1r);
            MMA_BF16(acc[0][2 * ntp + 1], aw0, b2r, b3r);
            MMA_BF16(acc[1][2 * ntp],     aw1, b0r, b1r);
            MMA_BF16(acc[1][2 * ntp + 1], aw1, b2r, b3r);
        }
    }
#pragma unroll
    for (int mi = 0; mi < 2; ++mi) {
        const int rm = wm * 32 + mi * 16 + mrow;
        const float bm  = b2[rm];
        const float bm8 = b2[rm + 8];
#pragma unroll
        for (int nt = 0; nt < 8; ++nt) {
            int col = wn * 64 + nt * 8 + (lane & 3) * 2;
            *(__nv_bfloat162*)&sH2[rm * 136 + col] = __floats2bfloat162_rn(
                fmaxf(acc[mi][nt][0] + bm, 0.f), fmaxf(acc[mi][nt][1] + bm, 0.f));
            *(__nv_bfloat162*)&sH2[(rm + 8) * 136 + col] = __floats2bfloat162_rn(
                fmaxf(acc[mi][nt][2] + bm8, 0.f), fmaxf(acc[mi][nt][3] + bm8, 0.f));
        }
    }
    __syncthreads();

    // ---- gemm3: delta = W3 @ h2 (all 8 warps; warp w -> cols w*16..+15) ----
    {
        const int w3m = lane >> 2;
        float acc3[2][4];
#pragma unroll
        for (int nt = 0; nt < 2; ++nt)
#pragma unroll
            for (int i = 0; i < 4; ++i) acc3[nt][i] = 0.f;

#pragma unroll
        for (int ks = 0; ks < 8; ++ks) {
            LDW(aw0, g_w3b, 128, w3m, ks * 16 + kq);
            uint32_t addr = smem_u32(&sH2[(ks * 16 + brow) * 136 + warp * 16 + bch]);
            uint32_t b0r, b1r, b2r, b3r;
            LDMX4T(b0r, b1r, b2r, b3r, addr);
            MMA_BF16(acc3[0], aw0, b0r, b1r);
            MMA_BF16(acc3[1], aw0, b2r, b3r);
        }
#pragma unroll
        for (int nt = 0; nt < 2; ++nt) {
            int col = warp * 16 + nt * 8 + (lane & 3) * 2;
            sD[w3m * 132 + col]     = acc3[nt][0];
            sD[w3m * 132 + col + 1] = acc3[nt][1];
            if (w3m + 8 < 12) {
                sD[(w3m + 8) * 132 + col]     = acc3[nt][2];
                sD[(w3m + 8) * 132 + col + 1] = acc3[nt][3];
            }
        }
    }
    __syncthreads();

    // ---- NCA epilogue: 128 voxels x 16 ch, 8 channels per thread ----
    {
        const int v   = tid & 127;
        const int grp = tid >> 7;          // 0: ch0-7, 1: ch8-15
        const int s   = (z << 12) + (y0 << 6) + v;

        const float* st = state + (size_t)b * NCH * SPAT;
        float* ot = out + (size_t)b * NCH * SPAT;

        if (grp == 0) {
            float e    = st[s];
            float anch = st[SPAT + s];
            float pos = (z >= 3) ? 1.f : anch;
            float legal = fminf(fmaxf((1.f - e) * pos, 0.f), 1.f);

            ot[0 * SPAT + s] = e;
            ot[1 * SPAT + s] = anch;
            ot[2 * SPAT + s] = st[2 * SPAT + s];
            ot[3 * SPAT + s] = st[3 * SPAT + s];
#pragma unroll
            for (int j = 0; j < 4; ++j) {
                float d = sD[j * 132 + v] + b3[j];
                float g = fminf(fmaxf(st[(4 + j) * SPAT + s] + 0.1f * d, 0.f), 1.f);
                if (j == 0) g = g * (1.f - e) * legal;
                ot[(4 + j) * SPAT + s] = g;
            }
        } else {
#pragma unroll
            for (int j = 4; j < 12; ++j) {
                float d = sD[j * 132 + v] + b3[j];
                float g = fminf(fmaxf(st[(4 + j) * SPAT + s] + 0.1f * d, 0.f), 1.f);
                ot[(4 + j) * SPAT + s] = g;
            }
        }
    }
}

// ---------------------------------------------------------------------------
extern "C" void kernel_launch(void* const* d_in, const int* in_sizes, int n_in,
                              void* d_out, int out_size) {
    const float* state = (const float*)d_in[0];
    const float* w1 = (const float*)d_in[1];
    const float* b1 = (const float*)d_in[2];
    const float* w2 = (const float*)d_in[3];
    const float* b2 = (const float*)d_in[4];
    const float* w3 = (const float*)d_in[5];
    const float* b3 = (const float*)d_in[6];
    float* out = (float*)d_out;

    cudaFuncSetAttribute(k_fused, cudaFuncAttributeMaxDynamicSharedMemorySize,
                         SMEM_BYTES);

    // 1) weights fp32 -> bf16
    k_convert<<<96, 256>>>(w1, w2, w3);

    // 2) fused perceive + MLP + epilogue (one block per 128 voxels)
    k_fused<<<NTOT / 128, 256, SMEM_BYTES>>>(state, b1, b2, b3, out);
}